// round 2
// baseline (speedup 1.0000x reference)
#include <cuda_runtime.h>
#include <cstdint>

#define BB 32
#define NI 512
#define NH 2048
#define NO 256
#define TT 1024

// ---------------- scratch (no allocations allowed) ----------------
__device__ uint32_t g_xbits[BB * TT * 16];   // x packed: [b][t][16 words]  (2 MB)
__device__ uint32_t g_s1bits[BB * TT * 64];  // spk1 packed: [b][t][64 words] (8 MB)
__device__ float    g_w2t[NH * NO];          // w2 transposed: [i][o] (2 MB)
__device__ float    g_cur2[BB * NO * TT];    // layer-2 currents (32 MB)

// ---------------- K1: pack x into bitmasks [b][t][16] ----------------
__global__ void k_pack_x(const float* __restrict__ x) {
    int bt = blockIdx.x * 256 + threadIdx.x;   // 32768 threads
    int b = bt >> 10, t = bt & 1023;
    const float* xp = x + ((size_t)b * NI) * TT + t;
    uint32_t* out = g_xbits + (size_t)bt * 16;
#pragma unroll 1
    for (int w = 0; w < 16; w++) {
        uint32_t word = 0;
#pragma unroll 8
        for (int j = 0; j < 32; j++)
            word |= (xp[(size_t)(w * 32 + j) * TT] > 0.5f) ? (1u << j) : 0u;
        out[w] = word;
    }
}

// ---------------- K0: transpose w2 (NO,NH) -> w2t (NH,NO) ----------------
__global__ void k_transpose_w2(const float* __restrict__ w2) {
    __shared__ float tile[32][33];
    int i0 = blockIdx.x * 32;  // over NH
    int o0 = blockIdx.y * 32;  // over NO
    int tx = threadIdx.x, ty = threadIdx.y;  // 32 x 8
    for (int r = ty; r < 32; r += 8)
        tile[r][tx] = w2[(size_t)(o0 + r) * NH + i0 + tx];  // coalesced over i
    __syncthreads();
    for (int r = ty; r < 32; r += 8)
        g_w2t[(size_t)(i0 + r) * NO + o0 + tx] = tile[tx][r];  // coalesced over o
}

// ---------------- K2: fused layer1 (sparse synapse + LIF) ----------------
// grid (NH/64, B), 256 threads, dynamic smem:
//   w1s  [512][68]  (139264 B)   weight tile, [i][o_local] padded
//   curb [64][68]   (17408 B)    current / spike staging per 64-t chunk
//   xw   [64][16]   (4096 B)     x bit words for the chunk
#define L1_SMEM (512 * 68 * 4 + 64 * 68 * 4 + 64 * 16 * 4)

__global__ void __launch_bounds__(256, 1) k_layer1(
    const float* __restrict__ w1, const float* __restrict__ b1,
    float* __restrict__ spk1) {
    extern __shared__ float smem[];
    float* w1s = smem;                       // 512*68
    float* curb = smem + 512 * 68;           // 64*68
    uint32_t* xw = (uint32_t*)(curb + 64 * 68);  // 64*16

    int tid = threadIdx.x;
    int b = blockIdx.y;
    int o0 = blockIdx.x * 64;

    // stage w1 tile: w1s[i*68 + ol] = w1[o0+ol][i]
    for (int idx = tid; idx < 64 * 512; idx += 256) {
        int ol = idx >> 9, i = idx & 511;
        w1s[i * 68 + ol] = w1[(size_t)(o0 + ol) * NI + i];
    }

    int og = tid & 7;    // 8 o's per thread: o = o0 + og*8 .. +7
    int tl = tid >> 3;   // 0..31 t-lane
    float bb0, bb1, bb2, bb3, bb4, bb5, bb6, bb7;
    {
        const float* bp = b1 + o0 + og * 8;
        bb0 = bp[0]; bb1 = bp[1]; bb2 = bp[2]; bb3 = bp[3];
        bb4 = bp[4]; bb5 = bp[5]; bb6 = bp[6]; bb7 = bp[7];
    }
    float v = 0.0f;  // LIF state (tid < 64 only meaningful)
    __syncthreads();

    for (int t0 = 0; t0 < TT; t0 += 64) {
        // stage x bit words for chunk
        for (int idx = tid; idx < 64 * 16; idx += 256)
            xw[idx] = g_xbits[((size_t)b * TT + t0) * 16 + idx];
        __syncthreads();

        // sparse accumulate: cur[t][o] = b1[o] + sum_{active i} w1[o][i]
#pragma unroll 1
        for (int tc = tl; tc < 64; tc += 32) {
            float a0 = bb0, a1 = bb1, a2 = bb2, a3 = bb3;
            float a4 = bb4, a5 = bb5, a6 = bb6, a7 = bb7;
            const uint32_t* ww = xw + tc * 16;
#pragma unroll 1
            for (int w = 0; w < 16; w++) {
                uint32_t word = ww[w];
                while (word) {
                    int j = __ffs(word) - 1;
                    word &= word - 1;
                    const float4* p =
                        (const float4*)&w1s[(w * 32 + j) * 68 + og * 8];
                    float4 A = p[0], C = p[1];
                    a0 += A.x; a1 += A.y; a2 += A.z; a3 += A.w;
                    a4 += C.x; a5 += C.y; a6 += C.z; a7 += C.w;
                }
            }
            float4* q = (float4*)&curb[tc * 68 + og * 8];
            q[0] = make_float4(a0, a1, a2, a3);
            q[1] = make_float4(a4, a5, a6, a7);
        }
        __syncthreads();

        // LIF over the 64-t chunk (threads 0..63 = one neuron each)
        if (tid < 64) {
#pragma unroll 1
            for (int tc = 0; tc < 64; tc++) {
                float c = curb[tc * 68 + tid];
                v = v * 0.95f + c;
                bool fire = (v >= 1.0f);
                v = fire ? 0.0f : v;
                curb[tc * 68 + tid] = fire ? 1.0f : 0.0f;
                uint32_t bal = __ballot_sync(0xffffffffu, fire);
                if ((tid & 31) == 0)
                    g_s1bits[((size_t)b * TT + t0 + tc) * 64 + (o0 >> 5) +
                             (tid >> 5)] = bal;
            }
        }
        __syncthreads();

        // write spk1 floats, coalesced per o-row
        for (int idx = tid; idx < 64 * 64; idx += 256) {
            int ol = idx >> 6, tc = idx & 63;
            spk1[((size_t)b * NH + o0 + ol) * TT + t0 + tc] =
                curb[tc * 68 + ol];
        }
        __syncthreads();
    }
}

// ---------------- K3: layer-2 currents (sparse, K-chunked smem) ----------------
// grid (T/64, B), 512 threads
//   w2s [128][256]  (131072 B), sw [64][4] words
#define L2_SMEM (128 * 256 * 4 + 64 * 4 * 4)

__global__ void __launch_bounds__(512, 1) k_layer2cur(const float* __restrict__ b2) {
    extern __shared__ float smem[];
    float* w2s = smem;                        // [i_local][o] 128*256
    uint32_t* sw = (uint32_t*)(smem + 128 * 256);  // [t_local][4]

    int tid = threadIdx.x;
    int b = blockIdx.y;
    int t0 = blockIdx.x * 64;
    int oq = (tid & 63) * 4;  // 4 o's per thread
    int th = tid >> 6;        // 0..7 -> t = t0 + th*8 + tt

    float acc[4][8];
    {
        const float* bp = b2 + oq;
        float bz0 = bp[0], bz1 = bp[1], bz2 = bp[2], bz3 = bp[3];
#pragma unroll
        for (int q = 0; q < 8; q++) {
            acc[0][q] = bz0; acc[1][q] = bz1; acc[2][q] = bz2; acc[3][q] = bz3;
        }
    }

#pragma unroll 1
    for (int kc = 0; kc < 16; kc++) {
        __syncthreads();
        // stage w2 chunk [128 i][256 o]
        {
            const float4* src = (const float4*)(g_w2t + (size_t)kc * 128 * NO);
            float4* dst = (float4*)w2s;
            for (int idx = tid; idx < 128 * 256 / 4; idx += 512)
                dst[idx] = src[idx];
        }
        // stage spike words for this chunk: 64 t x 4 words
        if (tid < 256) {
            int t_l = tid >> 2, w = tid & 3;
            sw[tid] = g_s1bits[((size_t)b * TT + t0 + t_l) * 64 + kc * 4 + w];
        }
        __syncthreads();

#pragma unroll
        for (int q = 0; q < 8; q++) {
            const uint32_t* wp = sw + (th * 8 + q) * 4;
#pragma unroll
            for (int w = 0; w < 4; w++) {
                uint32_t word = wp[w];
                while (word) {
                    int j = __ffs(word) - 1;
                    word &= word - 1;
                    float4 wv = *(const float4*)&w2s[(w * 32 + j) * NO + oq];
                    acc[0][q] += wv.x; acc[1][q] += wv.y;
                    acc[2][q] += wv.z; acc[3][q] += wv.w;
                }
            }
        }
    }

    // write cur2
#pragma unroll
    for (int k = 0; k < 4; k++) {
        float* dst = g_cur2 + ((size_t)b * NO + oq + k) * TT + t0 + th * 8;
        ((float4*)dst)[0] = make_float4(acc[k][0], acc[k][1], acc[k][2], acc[k][3]);
        ((float4*)dst)[1] = make_float4(acc[k][4], acc[k][5], acc[k][6], acc[k][7]);
    }
}

// ---------------- K4: LIF layer 2 ----------------
__global__ void k_lif2(float* __restrict__ spk2) {
    int bo = blockIdx.x * 256 + threadIdx.x;  // 8192 sequences
    const float4* cur = (const float4*)(g_cur2 + (size_t)bo * TT);
    float4* out = (float4*)(spk2 + (size_t)bo * TT);
    float v = 0.0f;
#pragma unroll 4
    for (int q = 0; q < TT / 4; q++) {
        float4 c = cur[q];
        float4 s;
        v = v * 0.95f + c.x; s.x = (v >= 1.0f) ? 1.0f : 0.0f; v = (v >= 1.0f) ? 0.0f : v;
        v = v * 0.95f + c.y; s.y = (v >= 1.0f) ? 1.0f : 0.0f; v = (v >= 1.0f) ? 0.0f : v;
        v = v * 0.95f + c.z; s.z = (v >= 1.0f) ? 1.0f : 0.0f; v = (v >= 1.0f) ? 0.0f : v;
        v = v * 0.95f + c.w; s.w = (v >= 1.0f) ? 1.0f : 0.0f; v = (v >= 1.0f) ? 0.0f : v;
        out[q] = s;
    }
}

// ---------------- launch ----------------
extern "C" void kernel_launch(void* const* d_in, const int* in_sizes, int n_in,
                              void* d_out, int out_size) {
    (void)in_sizes; (void)n_in; (void)out_size;
    const float* x  = (const float*)d_in[0];
    const float* w1 = (const float*)d_in[1];
    const float* b1 = (const float*)d_in[2];
    const float* w2 = (const float*)d_in[3];
    const float* b2 = (const float*)d_in[4];

    float* spk1 = (float*)d_out;                        // (32,2048,1024)
    float* spk2 = spk1 + (size_t)BB * NH * TT;          // (32,256,1024)

    cudaFuncSetAttribute(k_layer1, cudaFuncAttributeMaxDynamicSharedMemorySize, L1_SMEM);
    cudaFuncSetAttribute(k_layer2cur, cudaFuncAttributeMaxDynamicSharedMemorySize, L2_SMEM);

    k_pack_x<<<BB * TT / 256, 256>>>(x);
    k_transpose_w2<<<dim3(NH / 32, NO / 32), dim3(32, 8)>>>(w2);
    k_layer1<<<dim3(NH / 64, BB), 256, L1_SMEM>>>(w1, b1, spk1);
    k_layer2cur<<<dim3(TT / 64, BB), 512, L2_SMEM>>>(b2);
    k_lif2<<<BB * NO / 256, 256>>>(spk2);
}

// round 3
// speedup vs baseline: 1.1323x; 1.1323x over previous
#include <cuda_runtime.h>
#include <cstdint>

#define BB 32
#define NI 512
#define NH 2048
#define NO 256
#define TT 1024

// ---------------- scratch (no allocations allowed) ----------------
__device__ uint32_t g_xbits[BB * TT * 16];   // x packed: [b][t][16 words]  (2 MB)
__device__ uint32_t g_s1bits[BB * TT * 64];  // spk1 packed: [b][t][64 words] (8 MB)
__device__ float    g_w2t[NH * NO];          // w2 transposed: [i][o] (2 MB)
__device__ float    g_cur2[BB * NO * TT];    // layer-2 currents (32 MB)

#define BAR_SYNC(id, cnt)   asm volatile("bar.sync %0, %1;"   :: "r"(id), "r"(cnt) : "memory")
#define BAR_ARRIVE(id, cnt) asm volatile("bar.arrive %0, %1;" :: "r"(id), "r"(cnt) : "memory")

// ---------------- K1: pack x into bitmasks [b][t][16] ----------------
__global__ void k_pack_x(const float* __restrict__ x) {
    int bt = blockIdx.x * 256 + threadIdx.x;   // 32768 threads
    int b = bt >> 10, t = bt & 1023;
    const float* xp = x + ((size_t)b * NI) * TT + t;
    uint32_t* out = g_xbits + (size_t)bt * 16;
#pragma unroll 1
    for (int w = 0; w < 16; w++) {
        uint32_t word = 0;
#pragma unroll 8
        for (int j = 0; j < 32; j++)
            word |= (xp[(size_t)(w * 32 + j) * TT] > 0.5f) ? (1u << j) : 0u;
        out[w] = word;
    }
}

// ---------------- K0: transpose w2 (NO,NH) -> w2t (NH,NO) ----------------
__global__ void k_transpose_w2(const float* __restrict__ w2) {
    __shared__ float tile[32][33];
    int i0 = blockIdx.x * 32;  // over NH
    int o0 = blockIdx.y * 32;  // over NO
    int tx = threadIdx.x, ty = threadIdx.y;  // 32 x 8
    for (int r = ty; r < 32; r += 8)
        tile[r][tx] = w2[(size_t)(o0 + r) * NH + i0 + tx];  // coalesced over i
    __syncthreads();
    for (int r = ty; r < 32; r += 8)
        g_w2t[(size_t)(i0 + r) * NO + o0 + tx] = tile[tx][r];  // coalesced over o
}

// ---------------- K2: fused layer1, warp-specialized + double-buffered ----
// grid (NH/64, B), 576 threads:
//   tid 0..511  : accumulators. warp = one t (uniform bit words, no divergence),
//                 lane = 2 outputs (float2).
//   tid 512..575: LIF + spk1/s1bits writeout (one neuron per thread).
// smem: w1s [512][66] (pitch 66: aligned float2 reads, near-conflict-free
//       transposed staging), curb[2][64][64], xw[2][1024].
#define W1P 66
#define L1_SMEM (512 * W1P * 4 + 2 * 64 * 64 * 4 + 2 * 1024 * 4)
// named barriers: FULL0=1, FULL1=2, FREE0=3, FREE1=4, PROD=5

__global__ void __launch_bounds__(576, 1) k_layer1(
    const float* __restrict__ w1, const float* __restrict__ b1,
    float* __restrict__ spk1) {
    extern __shared__ float smem[];
    float* w1s = smem;                                // [512][66]
    float* curb = smem + 512 * W1P;                   // [2][64][64]
    uint32_t* xw = (uint32_t*)(curb + 2 * 64 * 64);   // [2][1024]

    int tid = threadIdx.x;
    int b = blockIdx.y;
    int o0 = blockIdx.x * 64;

    // stage w1 tile transposed: w1s[i][ol] = w1[o0+ol][i]
    // idx fast over i -> coalesced LDG; pitch 66 -> STS 2-way conflict only.
    for (int idx = tid; idx < 64 * 512; idx += 576) {
        int ol = idx >> 9, i = idx & 511;
        w1s[i * W1P + ol] = w1[(size_t)(o0 + ol) * NI + i];
    }
    __syncthreads();

    if (tid < 512) {
        // ---------------- producers ----------------
        int wid = tid >> 5, lane = tid & 31;
        float2 bias = *(const float2*)&b1[o0 + lane * 2];

        for (int k = 0; k < 16; k++) {
            int p = k & 1;
            int t0 = k * 64;
            if (k >= 2) BAR_SYNC(3 + p, 576);  // wait buffer free

            // stage x bit words for this chunk
            for (int idx = tid; idx < 1024; idx += 512)
                xw[p * 1024 + idx] = g_xbits[((size_t)b * TT + t0) * 16 + idx];
            BAR_SYNC(5, 512);  // producers only: staging visible

#pragma unroll 1
            for (int pass = 0; pass < 4; pass++) {
                int tc = wid * 4 + pass;  // warp-uniform t
                float a0 = bias.x, a1 = bias.y;
                const uint32_t* ww = &xw[p * 1024 + tc * 16];
#pragma unroll 1
                for (int w = 0; w < 16; w++) {
                    uint32_t word = ww[w];  // uniform across warp
                    while (word) {
                        int j = __ffs(word) - 1;
                        word &= word - 1;
                        float2 wv = *(const float2*)&w1s[
                            (unsigned)((w << 5) + j) * W1P + lane * 2];
                        a0 += wv.x; a1 += wv.y;
                    }
                }
                *(float2*)&curb[(p * 64 + tc) * 64 + lane * 2] =
                    make_float2(a0, a1);
            }
            BAR_ARRIVE(1 + p, 576);  // buffer full
        }
    } else {
        // ---------------- consumers: LIF + writeout ----------------
        int n = tid - 512;        // neuron 0..63
        int lw = n >> 5;          // warp half (s1bits word index)
        int lane = n & 31;
        float v = 0.0f;
        uint32_t* s1base = g_s1bits + ((size_t)b * TT) * 64 + (o0 >> 5) + lw;

        for (int k = 0; k < 16; k++) {
            int p = k & 1;
            int t0 = k * 64;
            BAR_SYNC(1 + p, 576);  // wait buffer full

            uint32_t sp0 = 0, sp1 = 0;
#pragma unroll 1
            for (int tc = 0; tc < 64; tc++) {
                float c = curb[(p * 64 + tc) * 64 + n];
                v = v * 0.95f + c;
                bool fire = (v >= 1.0f);
                v = fire ? 0.0f : v;
                uint32_t bal = __ballot_sync(0xffffffffu, fire);
                if (lane == 0) s1base[(size_t)(t0 + tc) * 64] = bal;
                if (tc < 32) sp0 |= (fire ? 1u : 0u) << tc;
                else         sp1 |= (fire ? 1u : 0u) << (tc - 32);
            }
            BAR_ARRIVE(3 + p, 576);  // buffer free (spikes now in regs)

            // coalesced writeout: warp walks its 32 rows, lanes cover t
#pragma unroll 1
            for (int r = 0; r < 32; r++) {
                uint32_t w0 = __shfl_sync(0xffffffffu, sp0, r);
                uint32_t w1b = __shfl_sync(0xffffffffu, sp1, r);
                int o = o0 + lw * 32 + r;
                int tb = lane * 2;
                uint64_t bits = ((uint64_t)w1b << 32) | (uint64_t)w0;
                float f0 = ((bits >> tb) & 1ull) ? 1.0f : 0.0f;
                float f1 = ((bits >> (tb + 1)) & 1ull) ? 1.0f : 0.0f;
                *(float2*)&spk1[((size_t)b * NH + o) * TT + t0 + tb] =
                    make_float2(f0, f1);
            }
        }
    }
}

// ---------------- K3: layer-2 currents (64-row chunks, 2 CTAs/SM) --------
// grid (T/64, B), 512 threads
//   w2s [64][256] (65536 B), sw [64][2] words (512 B)
#define L2_SMEM (64 * 256 * 4 + 64 * 2 * 4)

__global__ void __launch_bounds__(512, 2) k_layer2cur(const float* __restrict__ b2) {
    extern __shared__ float smem[];
    float* w2s = smem;                             // [i_local][o] 64*256
    uint32_t* sw = (uint32_t*)(smem + 64 * 256);   // [t_local][2]

    int tid = threadIdx.x;
    int b = blockIdx.y;
    int t0 = blockIdx.x * 64;
    int oq = (tid & 63) * 4;  // 4 o's per thread
    int th = tid >> 6;        // 0..7 -> t = t0 + th*8 + q

    float acc[4][8];
    {
        const float* bp = b2 + oq;
        float bz0 = bp[0], bz1 = bp[1], bz2 = bp[2], bz3 = bp[3];
#pragma unroll
        for (int q = 0; q < 8; q++) {
            acc[0][q] = bz0; acc[1][q] = bz1; acc[2][q] = bz2; acc[3][q] = bz3;
        }
    }

#pragma unroll 1
    for (int kc = 0; kc < 32; kc++) {
        __syncthreads();
        // stage w2 chunk [64 i][256 o] = 64 KB
        {
            const float4* src = (const float4*)(g_w2t + (size_t)kc * 64 * NO);
            float4* dst = (float4*)w2s;
            for (int idx = tid; idx < 64 * 256 / 4; idx += 512)
                dst[idx] = src[idx];
        }
        // stage spike words: 64 t x 2 words
        if (tid < 128) {
            int t_l = tid >> 1, w = tid & 1;
            sw[tid] = g_s1bits[((size_t)b * TT + t0 + t_l) * 64 + kc * 2 + w];
        }
        __syncthreads();

#pragma unroll
        for (int q = 0; q < 8; q++) {
            const uint32_t* wp = sw + (th * 8 + q) * 2;
#pragma unroll
            for (int w = 0; w < 2; w++) {
                uint32_t word = wp[w];
                while (word) {
                    int j = __ffs(word) - 1;
                    word &= word - 1;
                    float4 wv = *(const float4*)&w2s[(w * 32 + j) * NO + oq];
                    acc[0][q] += wv.x; acc[1][q] += wv.y;
                    acc[2][q] += wv.z; acc[3][q] += wv.w;
                }
            }
        }
    }

    // write cur2
#pragma unroll
    for (int k = 0; k < 4; k++) {
        float* dst = g_cur2 + ((size_t)b * NO + oq + k) * TT + t0 + th * 8;
        ((float4*)dst)[0] = make_float4(acc[k][0], acc[k][1], acc[k][2], acc[k][3]);
        ((float4*)dst)[1] = make_float4(acc[k][4], acc[k][5], acc[k][6], acc[k][7]);
    }
}

// ---------------- K4: LIF layer 2 (prefetch, wide spread) ----------------
__global__ void k_lif2(float* __restrict__ spk2) {
    int bo = blockIdx.x * 64 + threadIdx.x;  // 8192 sequences, 128 blocks
    const float4* cur = (const float4*)(g_cur2 + (size_t)bo * TT);
    float4* out = (float4*)(spk2 + (size_t)bo * TT);
    float v = 0.0f;
    float4 c = cur[0];
#pragma unroll 4
    for (int q = 0; q < TT / 4; q++) {
        float4 cn = (q < TT / 4 - 1) ? cur[q + 1] : make_float4(0.f, 0.f, 0.f, 0.f);
        float4 s;
        v = v * 0.95f + c.x; s.x = (v >= 1.0f) ? 1.0f : 0.0f; v = (v >= 1.0f) ? 0.0f : v;
        v = v * 0.95f + c.y; s.y = (v >= 1.0f) ? 1.0f : 0.0f; v = (v >= 1.0f) ? 0.0f : v;
        v = v * 0.95f + c.z; s.z = (v >= 1.0f) ? 1.0f : 0.0f; v = (v >= 1.0f) ? 0.0f : v;
        v = v * 0.95f + c.w; s.w = (v >= 1.0f) ? 1.0f : 0.0f; v = (v >= 1.0f) ? 0.0f : v;
        out[q] = s;
        c = cn;
    }
}

// ---------------- launch ----------------
extern "C" void kernel_launch(void* const* d_in, const int* in_sizes, int n_in,
                              void* d_out, int out_size) {
    (void)in_sizes; (void)n_in; (void)out_size;
    const float* x  = (const float*)d_in[0];
    const float* w1 = (const float*)d_in[1];
    const float* b1 = (const float*)d_in[2];
    const float* w2 = (const float*)d_in[3];
    const float* b2 = (const float*)d_in[4];

    float* spk1 = (float*)d_out;                        // (32,2048,1024)
    float* spk2 = spk1 + (size_t)BB * NH * TT;          // (32,256,1024)

    cudaFuncSetAttribute(k_layer1, cudaFuncAttributeMaxDynamicSharedMemorySize, L1_SMEM);
    cudaFuncSetAttribute(k_layer2cur, cudaFuncAttributeMaxDynamicSharedMemorySize, L2_SMEM);

    k_pack_x<<<BB * TT / 256, 256>>>(x);
    k_transpose_w2<<<dim3(NH / 32, NO / 32), dim3(32, 8)>>>(w2);
    k_layer1<<<dim3(NH / 64, BB), 576, L1_SMEM>>>(w1, b1, spk1);
    k_layer2cur<<<dim3(TT / 64, BB), 512, L2_SMEM>>>(b2);
    k_lif2<<<BB * NO / 64, 64>>>(spk2);
}

// round 5
// speedup vs baseline: 2.0902x; 1.8460x over previous
#include <cuda_runtime.h>
#include <cstdint>

#define BB 32
#define NI 512
#define NH 2048
#define NO 256
#define TT 1024

// ---------------- scratch (no allocations allowed) ----------------
__device__ uint32_t g_s1bits[BB * TT * 64];  // spk1 packed: [b][t][64 words] (8 MB)
__device__ float    g_w2t[NH * NO];          // w2 transposed: [i][o] (2 MB)
__device__ float    g_cur2[BB * NO * TT];    // layer-2 currents (32 MB)
__device__ uint16_t g_xidx[(size_t)BB * TT * 512];  // per-(b,t) active-input lists (32 MB)
__device__ int      g_xcnt[BB * TT];                // counts (128 KB)

#define BAR_SYNC(id, cnt)   asm volatile("bar.sync %0, %1;"   :: "r"(id), "r"(cnt) : "memory")
#define BAR_ARRIVE(id, cnt) asm volatile("bar.arrive %0, %1;" :: "r"(id), "r"(cnt) : "memory")

// ---------------- K1: build active-input index lists per (b,t) -----------
__global__ void k_build_lists(const float* __restrict__ x) {
    int bt = blockIdx.x * 256 + threadIdx.x;   // 32768 threads
    int b = bt >> 10, t = bt & 1023;
    const float* xp = x + ((size_t)b * NI) * TT + t;
    uint16_t* out = g_xidx + (size_t)bt * 512;
    int n = 0;
#pragma unroll 8
    for (int i = 0; i < NI; i++) {
        if (xp[(size_t)i * TT] > 0.5f) out[n++] = (uint16_t)i;
    }
    g_xcnt[bt] = n;
}

// ---------------- K0: transpose w2 (NO,NH) -> w2t (NH,NO) ----------------
__global__ void k_transpose_w2(const float* __restrict__ w2) {
    __shared__ float tile[32][33];
    int i0 = blockIdx.x * 32;  // over NH
    int o0 = blockIdx.y * 32;  // over NO
    int tx = threadIdx.x, ty = threadIdx.y;  // 32 x 8
    for (int r = ty; r < 32; r += 8)
        tile[r][tx] = w2[(size_t)(o0 + r) * NH + i0 + tx];
    __syncthreads();
    for (int r = ty; r < 32; r += 8)
        g_w2t[(size_t)(i0 + r) * NO + o0 + tx] = tile[tx][r];
}

// ---------------- K2: fused layer1, list-driven, double-buffered ---------
// 576 threads: tid 0..511 accumulators (warp = one t, lane = 2 outputs),
//              tid 512..575 LIF + writeout.
// smem: w1s[512][66] 135168 B, curb[2][64][64] 32768 B,
//       lists: idx[2][64][128] u16 (32768 B) + cnt[2][64] (512 B)
#define W1P 66
#define L1_SMEM (512 * W1P * 4 + 2 * 64 * 64 * 4 + 2 * 64 * 128 * 2 + 2 * 64 * 4)
// named barriers: FULL0=1, FULL1=2, FREE0=3, FREE1=4, PROD=5

__global__ void __launch_bounds__(576, 1) k_layer1(
    const float* __restrict__ w1, const float* __restrict__ b1,
    float* __restrict__ spk1) {
    extern __shared__ float smem[];
    float* w1s = smem;                                   // [512][66]
    float* curb = smem + 512 * W1P;                      // [2][64][64]
    uint16_t* lidx = (uint16_t*)(curb + 2 * 64 * 64);    // [2][64][128]
    int* lcnt = (int*)(lidx + 2 * 64 * 128);             // [2][64]

    int tid = threadIdx.x;
    int b = blockIdx.y;
    int o0 = blockIdx.x * 64;

    // stage w1 tile transposed: w1s[i][ol] = w1[o0+ol][i] (coalesced over i)
    for (int idx = tid; idx < 64 * 512; idx += 576) {
        int ol = idx >> 9, i = idx & 511;
        w1s[i * W1P + ol] = w1[(size_t)(o0 + ol) * NI + i];
    }
    __syncthreads();

    if (tid < 512) {
        // ---------------- producers ----------------
        int wid = tid >> 5, lane = tid & 31;
        float2 bias = *(const float2*)&b1[o0 + lane * 2];
        const float* wrow = w1s + lane * 2;

        for (int k = 0; k < 16; k++) {
            int p = k & 1;
            size_t bt0 = (size_t)b * TT + k * 64;
            if (k >= 2) BAR_SYNC(3 + p, 576);  // wait buffer free

            // stage lists: first 128 idx of each of 64 t, as uint32 pairs
            {
                const uint32_t* src = (const uint32_t*)(g_xidx + bt0 * 512);
                uint32_t* dst = (uint32_t*)(lidx + (size_t)p * 64 * 128);
                for (int m = tid; m < 64 * 64; m += 512) {
                    int tl = m >> 6, c = m & 63;
                    dst[tl * 64 + c] = src[tl * 256 + c];
                }
                if (tid < 64) lcnt[p * 64 + tid] = g_xcnt[bt0 + tid];
            }
            BAR_SYNC(5, 512);  // producers only: staging visible

#pragma unroll 1
            for (int pass = 0; pass < 4; pass++) {
                int tc = wid * 4 + pass;  // warp-uniform t
                int n = lcnt[p * 64 + tc];
                const uint16_t* lp = lidx + (p * 64 + tc) * 128;
                float a0 = bias.x, a1 = bias.y;
                int nn = n < 128 ? n : 128;
                int m = 0;
#pragma unroll 1
                for (; m + 4 <= nn; m += 4) {
                    uint32_t p01 = *(const uint32_t*)&lp[m];
                    uint32_t p23 = *(const uint32_t*)&lp[m + 2];
                    float2 w0 = *(const float2*)&wrow[(p01 & 0xffffu) * W1P];
                    float2 w1v = *(const float2*)&wrow[(p01 >> 16) * W1P];
                    float2 w2v = *(const float2*)&wrow[(p23 & 0xffffu) * W1P];
                    float2 w3 = *(const float2*)&wrow[(p23 >> 16) * W1P];
                    a0 += w0.x; a1 += w0.y;
                    a0 += w1v.x; a1 += w1v.y;
                    a0 += w2v.x; a1 += w2v.y;
                    a0 += w3.x; a1 += w3.y;
                }
                for (; m < nn; m++) {
                    float2 wv = *(const float2*)&wrow[(uint32_t)lp[m] * W1P];
                    a0 += wv.x; a1 += wv.y;
                }
                // extremely rare overflow path (count > 128): exact fallback
                for (; m < n; m++) {
                    uint32_t i = g_xidx[(bt0 + tc) * 512 + m];
                    float2 wv = *(const float2*)&wrow[i * W1P];
                    a0 += wv.x; a1 += wv.y;
                }
                *(float2*)&curb[(p * 64 + tc) * 64 + lane * 2] =
                    make_float2(a0, a1);
            }
            BAR_ARRIVE(1 + p, 576);  // buffer full
        }
    } else {
        // ---------------- consumers: LIF + writeout ----------------
        int n = tid - 512;        // neuron 0..63
        int lw = n >> 5;          // which 32-neuron word
        int lane = n & 31;
        float v = 0.0f;
        uint32_t* s1base = g_s1bits + ((size_t)b * TT) * 64 + (o0 >> 5) + lw;

        for (int k = 0; k < 16; k++) {
            int p = k & 1;
            int t0 = k * 64;
            BAR_SYNC(1 + p, 576);  // wait buffer full

            uint32_t sp0 = 0, sp1 = 0;
#pragma unroll 1
            for (int tc = 0; tc < 64; tc++) {
                float c = curb[(p * 64 + tc) * 64 + n];
                v = v * 0.95f + c;
                bool fire = (v >= 1.0f);
                v = fire ? 0.0f : v;
                uint32_t bal = __ballot_sync(0xffffffffu, fire);
                if (lane == 0) s1base[(size_t)(t0 + tc) * 64] = bal;
                if (tc < 32) sp0 |= (fire ? 1u : 0u) << tc;
                else         sp1 |= (fire ? 1u : 0u) << (tc - 32);
            }
            BAR_ARRIVE(3 + p, 576);  // buffer free (spikes now in regs)

            // coalesced writeout: warp walks its 32 rows, lanes cover t
#pragma unroll 1
            for (int r = 0; r < 32; r++) {
                uint32_t w0 = __shfl_sync(0xffffffffu, sp0, r);
                uint32_t w1b = __shfl_sync(0xffffffffu, sp1, r);
                int o = o0 + lw * 32 + r;
                int tb = lane * 2;
                uint64_t bits = ((uint64_t)w1b << 32) | (uint64_t)w0;
                float f0 = ((bits >> tb) & 1ull) ? 1.0f : 0.0f;
                float f1 = ((bits >> (tb + 1)) & 1ull) ? 1.0f : 0.0f;
                *(float2*)&spk1[((size_t)b * NH + o) * TT + t0 + tb] =
                    make_float2(f0, f1);
            }
        }
    }
}

// ---------------- K3: layer-2 currents (64-row chunks, 2 CTAs/SM) --------
#define L2_SMEM (64 * 256 * 4 + 64 * 2 * 4)

__global__ void __launch_bounds__(512, 2) k_layer2cur(const float* __restrict__ b2) {
    extern __shared__ float smem[];
    float* w2s = smem;                             // [i_local][o] 64*256
    uint32_t* sw = (uint32_t*)(smem + 64 * 256);   // [t_local][2]

    int tid = threadIdx.x;
    int b = blockIdx.y;
    int t0 = blockIdx.x * 64;
    int oq = (tid & 63) * 4;
    int th = tid >> 6;

    float acc[4][8];
    {
        const float* bp = b2 + oq;
        float bz0 = bp[0], bz1 = bp[1], bz2 = bp[2], bz3 = bp[3];
#pragma unroll
        for (int q = 0; q < 8; q++) {
            acc[0][q] = bz0; acc[1][q] = bz1; acc[2][q] = bz2; acc[3][q] = bz3;
        }
    }

#pragma unroll 1
    for (int kc = 0; kc < 32; kc++) {
        __syncthreads();
        {
            const float4* src = (const float4*)(g_w2t + (size_t)kc * 64 * NO);
            float4* dst = (float4*)w2s;
            for (int idx = tid; idx < 64 * 256 / 4; idx += 512)
                dst[idx] = src[idx];
        }
        if (tid < 128) {
            int t_l = tid >> 1, w = tid & 1;
            sw[tid] = g_s1bits[((size_t)b * TT + t0 + t_l) * 64 + kc * 2 + w];
        }
        __syncthreads();

#pragma unroll
        for (int q = 0; q < 8; q++) {
            const uint32_t* wp = sw + (th * 8 + q) * 2;
#pragma unroll
            for (int w = 0; w < 2; w++) {
                uint32_t word = wp[w];
                while (word) {
                    int j = __ffs(word) - 1;
                    word &= word - 1;
                    float4 wv = *(const float4*)&w2s[(w * 32 + j) * NO + oq];
                    acc[0][q] += wv.x; acc[1][q] += wv.y;
                    acc[2][q] += wv.z; acc[3][q] += wv.w;
                }
            }
        }
    }

#pragma unroll
    for (int k = 0; k < 4; k++) {
        float* dst = g_cur2 + ((size_t)b * NO + oq + k) * TT + t0 + th * 8;
        ((float4*)dst)[0] = make_float4(acc[k][0], acc[k][1], acc[k][2], acc[k][3]);
        ((float4*)dst)[1] = make_float4(acc[k][4], acc[k][5], acc[k][6], acc[k][7]);
    }
}

// ---------------- K4: LIF layer 2 (4-deep load batches) ------------------
__global__ void k_lif2(float* __restrict__ spk2) {
    int bo = blockIdx.x * 128 + threadIdx.x;  // 8192 sequences
    const float4* cur = (const float4*)(g_cur2 + (size_t)bo * TT);
    float4* out = (float4*)(spk2 + (size_t)bo * TT);
    float v = 0.0f;
#pragma unroll 1
    for (int q = 0; q < TT / 4; q += 4) {
        float4 c0 = cur[q], c1 = cur[q + 1], c2 = cur[q + 2], c3 = cur[q + 3];
        float4 s;
#define LIFSTEP(cc, ss) \
        v = v * 0.95f + (cc); (ss) = (v >= 1.0f) ? 1.0f : 0.0f; v = (v >= 1.0f) ? 0.0f : v;
        LIFSTEP(c0.x, s.x) LIFSTEP(c0.y, s.y) LIFSTEP(c0.z, s.z) LIFSTEP(c0.w, s.w)
        out[q] = s;
        LIFSTEP(c1.x, s.x) LIFSTEP(c1.y, s.y) LIFSTEP(c1.z, s.z) LIFSTEP(c1.w, s.w)
        out[q + 1] = s;
        LIFSTEP(c2.x, s.x) LIFSTEP(c2.y, s.y) LIFSTEP(c2.z, s.z) LIFSTEP(c2.w, s.w)
        out[q + 2] = s;
        LIFSTEP(c3.x, s.x) LIFSTEP(c3.y, s.y) LIFSTEP(c3.z, s.z) LIFSTEP(c3.w, s.w)
        out[q + 3] = s;
#undef LIFSTEP
    }
}

// ---------------- launch ----------------
extern "C" void kernel_launch(void* const* d_in, const int* in_sizes, int n_in,
                              void* d_out, int out_size) {
    (void)in_sizes; (void)n_in; (void)out_size;
    const float* x  = (const float*)d_in[0];
    const float* w1 = (const float*)d_in[1];
    const float* b1 = (const float*)d_in[2];
    const float* w2 = (const float*)d_in[3];
    const float* b2 = (const float*)d_in[4];

    float* spk1 = (float*)d_out;                        // (32,2048,1024)
    float* spk2 = spk1 + (size_t)BB * NH * TT;          // (32,256,1024)

    cudaFuncSetAttribute(k_layer1, cudaFuncAttributeMaxDynamicSharedMemorySize, L1_SMEM);
    cudaFuncSetAttribute(k_layer2cur, cudaFuncAttributeMaxDynamicSharedMemorySize, L2_SMEM);

    k_build_lists<<<BB * TT / 256, 256>>>(x);
    k_transpose_w2<<<dim3(NH / 32, NO / 32), dim3(32, 8)>>>(w2);
    k_layer1<<<dim3(NH / 64, BB), 576, L1_SMEM>>>(w1, b1, spk1);
    k_layer2cur<<<dim3(TT / 64, BB), 512, L2_SMEM>>>(b2);
    k_lif2<<<BB * NO / 128, 128>>>(spk2);
}